// round 9
// baseline (speedup 1.0000x reference)
#include <cuda_runtime.h>
#include <cuda_fp16.h>

#define NN 100000
#define NE 1200000
#define DD 64
#define ADJ_STRIDE 32
#define OVF_CAP 8192
#define NTM 782                 // ceil(100000/128) GEMM tiles
#define SW128(o) ((o) ^ ((((o) >> 3)) & 0x70))

typedef unsigned long long u64;

// Scratch (device globals — no allocation allowed)
__device__ __half g_Hh  [NN * DD];        // layer-1 gather source (feats*nout)
__device__ __half g_H2h [NN * DD];        // layer-2 gather source
__device__ __half g_AGGh[NN * DD];        // gather output = GEMM A operand
__device__ int   g_degout[NN];
__device__ int   g_cnt[NN];
__device__ float g_nout[NN];
__device__ float g_nin[NN];
__device__ int   g_adj[NN * ADJ_STRIDE];
__device__ int   g_ovf[OVF_CAP];
__device__ int   g_ovf_cnt;

// ---------------------------------------------------------------------------
__global__ void k_zero() {
    int i = blockIdx.x * blockDim.x + threadIdx.x;
    if (i < NN) { g_degout[i] = 0; g_cnt[i] = 0; }
    if (i == 0) g_ovf_cnt = 0;
}

// 4 edges per thread (int4 loads) for atomic-latency MLP.
__global__ void k_build(const int4* __restrict__ src4, const int4* __restrict__ dst4) {
    int e4 = blockIdx.x * blockDim.x + threadIdx.x;
    if (e4 >= NE / 4) return;
    int4 s = src4[e4];
    int4 d = dst4[e4];
    atomicAdd(&g_degout[s.x], 1);
    atomicAdd(&g_degout[s.y], 1);
    atomicAdd(&g_degout[s.z], 1);
    atomicAdd(&g_degout[s.w], 1);
    int c0 = atomicAdd(&g_cnt[d.x], 1);
    int c1 = atomicAdd(&g_cnt[d.y], 1);
    int c2 = atomicAdd(&g_cnt[d.z], 1);
    int c3 = atomicAdd(&g_cnt[d.w], 1);
    int base = e4 * 4;
    if (c0 < ADJ_STRIDE) g_adj[d.x * ADJ_STRIDE + c0] = s.x;
    else { int o = atomicAdd(&g_ovf_cnt, 1); if (o < OVF_CAP) g_ovf[o] = base; }
    if (c1 < ADJ_STRIDE) g_adj[d.y * ADJ_STRIDE + c1] = s.y;
    else { int o = atomicAdd(&g_ovf_cnt, 1); if (o < OVF_CAP) g_ovf[o] = base + 1; }
    if (c2 < ADJ_STRIDE) g_adj[d.z * ADJ_STRIDE + c2] = s.z;
    else { int o = atomicAdd(&g_ovf_cnt, 1); if (o < OVF_CAP) g_ovf[o] = base + 2; }
    if (c3 < ADJ_STRIDE) g_adj[d.w * ADJ_STRIDE + c3] = s.w;
    else { int o = atomicAdd(&g_ovf_cnt, 1); if (o < OVF_CAP) g_ovf[o] = base + 3; }
}

// Fused norm + scale: Hh[row] = half(feats[row] * nout[row]); persists norms.
// 2 float4 per thread; each row's 16 lanes recompute rsqrt (MUFU, cheap).
__global__ void k_scale(const float4* __restrict__ feats) {
    int t0 = (blockIdx.x * blockDim.x + threadIdx.x) * 2;
    if (t0 >= NN * 16) return;
    #pragma unroll
    for (int q = 0; q < 2; q++) {
        int t = t0 + q;
        int row = t >> 4;
        float s = rsqrtf(fmaxf((float)g_degout[row], 1.0f));
        if ((t & 15) == 0) {
            g_nout[row] = s;
            g_nin[row] = rsqrtf(fmaxf((float)g_cnt[row], 1.0f));
        }
        float4 v = feats[t];
        __half2 h0 = __floats2half2_rn(v.x * s, v.y * s);
        __half2 h1 = __floats2half2_rn(v.z * s, v.w * s);
        uint2 u;
        u.x = *reinterpret_cast<unsigned*>(&h0);
        u.y = *reinterpret_cast<unsigned*>(&h1);
        reinterpret_cast<uint2*>(g_Hh)[t] = u;
    }
}

__device__ __forceinline__ void acc4h(float4& a, uint2 u) {
    float2 f0 = __half22float2(*reinterpret_cast<__half2*>(&u.x));
    float2 f1 = __half22float2(*reinterpret_cast<__half2*>(&u.y));
    a.x += f0.x; a.y += f0.y; a.z += f1.x; a.w += f1.y;
}

// Gather: AGGh[n] = half( (sum_{s in adj[n]} H[s]) * nin[n] )
template <int LAYER>
__global__ void __launch_bounds__(256) k_agg(const int* __restrict__ src,
                                             const int* __restrict__ dst) {
    int t = blockIdx.x * blockDim.x + threadIdx.x;
    if (t >= NN * 16) return;
    int n = t >> 4, j = t & 15;
    const uint2* Hv = reinterpret_cast<const uint2*>(LAYER == 1 ? g_Hh : g_H2h);
    int cnt = g_cnt[n];
    int lim = cnt < ADJ_STRIDE ? cnt : ADJ_STRIDE;
    const int* lst = &g_adj[n * ADJ_STRIDE];
    float4 acc = make_float4(0.f, 0.f, 0.f, 0.f);
    int k = 0;
    for (; k + 4 <= lim; k += 4) {
        int4 s4 = *reinterpret_cast<const int4*>(&lst[k]);
        uint2 u0 = Hv[s4.x * 16 + j];
        uint2 u1 = Hv[s4.y * 16 + j];
        uint2 u2 = Hv[s4.z * 16 + j];
        uint2 u3 = Hv[s4.w * 16 + j];
        acc4h(acc, u0); acc4h(acc, u1); acc4h(acc, u2); acc4h(acc, u3);
    }
    for (; k < lim; k++) acc4h(acc, Hv[__ldg(&lst[k]) * 16 + j]);
    if (cnt > ADJ_STRIDE) {
        int oc = g_ovf_cnt; if (oc > OVF_CAP) oc = OVF_CAP;
        for (int i = 0; i < oc; i++) {
            int e = g_ovf[i];
            if (dst[e] == n) acc4h(acc, Hv[src[e] * 16 + j]);
        }
    }
    float s = g_nin[n];
    __half2 h0 = __floats2half2_rn(acc.x * s, acc.y * s);
    __half2 h1 = __floats2half2_rn(acc.z * s, acc.w * s);
    uint2 u;
    u.x = *reinterpret_cast<unsigned*>(&h0);
    u.y = *reinterpret_cast<unsigned*>(&h1);
    reinterpret_cast<uint2*>(g_AGGh)[t] = u;
}

// ---------------------------------------------------------------------------
// Warp-MMA GEMM (HMMA): D(128x64) = A(128x64) @ W(64x64)
__device__ __forceinline__ unsigned smem_u32(const void* p) {
    unsigned a;
    asm("{ .reg .u64 t; cvta.to.shared.u64 t, %1; cvt.u32.u64 %0, t; }" : "=r"(a) : "l"(p));
    return a;
}
__device__ __forceinline__ void ldmx4(unsigned& r0, unsigned& r1, unsigned& r2,
                                      unsigned& r3, unsigned addr) {
    asm volatile("ldmatrix.sync.aligned.m8n8.x4.shared.b16 {%0,%1,%2,%3}, [%4];"
                 : "=r"(r0), "=r"(r1), "=r"(r2), "=r"(r3) : "r"(addr));
}
__device__ __forceinline__ void mma16816(float* d, unsigned a0, unsigned a1,
                                         unsigned a2, unsigned a3,
                                         unsigned b0, unsigned b1) {
    asm volatile(
        "mma.sync.aligned.m16n8k16.row.col.f32.f16.f16.f32 "
        "{%0,%1,%2,%3}, {%4,%5,%6,%7}, {%8,%9}, {%0,%1,%2,%3};"
        : "+f"(d[0]), "+f"(d[1]), "+f"(d[2]), "+f"(d[3])
        : "r"(a0), "r"(a1), "r"(a2), "r"(a3), "r"(b0), "r"(b1));
}

template <int LAYER>
__global__ void __launch_bounds__(128)
k_gemm_mma(const float* __restrict__ W, const float* __restrict__ bias,
           float* __restrict__ out_param) {
    __shared__ __align__(16) __half sA[128 * 64];
    __shared__ __align__(16) __half sB[64 * 64];
    __shared__ float bs[64];

    const int t = threadIdx.x;
    const int wid = t >> 5, lane = t & 31;

    for (int i = t; i < 4096; i += 128) {
        int k = i >> 6, c = i & 63;
        *reinterpret_cast<__half*>(
            reinterpret_cast<char*>(sB) + SW128(c * 128 + k * 2)) = __float2half_rn(W[i]);
    }
    if (t < 64) bs[t] = bias[t];

    int gr = blockIdx.x * 128 + t;
    {
        const uint4* a4 = reinterpret_cast<const uint4*>(g_AGGh);
        #pragma unroll
        for (int ch = 0; ch < 8; ch++) {
            uint4 v = make_uint4(0u, 0u, 0u, 0u);
            if (gr < NN) v = a4[gr * 8 + ch];
            *reinterpret_cast<uint4*>(
                reinterpret_cast<char*>(sA) + SW128(t * 128 + ch * 16)) = v;
        }
    }
    __syncthreads();

    const unsigned baseA = smem_u32(sA);
    const unsigned baseB = smem_u32(sB);
    const int lrow = lane & 15;
    const int lcol = (lane >> 4) * 16;

    float d[2][8][4];
    #pragma unroll
    for (int i = 0; i < 2; i++)
        #pragma unroll
        for (int j = 0; j < 8; j++)
            #pragma unroll
            for (int q = 0; q < 4; q++) d[i][j][q] = 0.f;

    #pragma unroll
    for (int kk = 0; kk < 4; kk++) {
        unsigned a[2][4];
        #pragma unroll
        for (int i = 0; i < 2; i++) {
            int row = wid * 32 + i * 16 + lrow;
            unsigned addr = baseA + SW128(row * 128 + kk * 32 + lcol);
            ldmx4(a[i][0], a[i][1], a[i][2], a[i][3], addr);
        }
        #pragma unroll
        for (int p = 0; p < 4; p++) {
            unsigned r0, r1, r2, r3;
            int nrow = p * 16 + lrow;
            unsigned addr = baseB + SW128(nrow * 128 + kk * 32 + lcol);
            ldmx4(r0, r1, r2, r3, addr);
            #pragma unroll
            for (int i = 0; i < 2; i++) {
                mma16816(d[i][p * 2 + 0], a[i][0], a[i][1], a[i][2], a[i][3], r0, r2);
                mma16816(d[i][p * 2 + 1], a[i][0], a[i][1], a[i][2], a[i][3], r1, r3);
            }
        }
    }

    const int g   = lane >> 2;
    const int tid = lane & 3;
    #pragma unroll
    for (int i = 0; i < 2; i++) {
        #pragma unroll
        for (int half = 0; half < 2; half++) {
            int row = blockIdx.x * 128 + wid * 32 + i * 16 + g + half * 8;
            if (row >= NN) continue;
            float no = (LAYER == 1) ? g_nout[row] : 0.f;
            #pragma unroll
            for (int j = 0; j < 8; j++) {
                int c = j * 8 + tid * 2;
                float v0 = d[i][j][half * 2 + 0] + bs[c];
                float v1 = d[i][j][half * 2 + 1] + bs[c + 1];
                if (LAYER == 1) {
                    v0 = fmaxf(v0, 0.f) * no;
                    v1 = fmaxf(v1, 0.f) * no;
                    __half2 h = __floats2half2_rn(v0, v1);
                    *reinterpret_cast<__half2*>(&g_H2h[row * DD + c]) = h;
                } else {
                    *reinterpret_cast<float2*>(&out_param[row * DD + c]) =
                        make_float2(v0, v1);
                }
            }
        }
    }
}

// ---------------------------------------------------------------------------
extern "C" void kernel_launch(void* const* d_in, const int* in_sizes, int n_in,
                              void* d_out, int out_size) {
    const float* feats = 0;
    const int *edgeA = 0, *edgeB = 0;
    const float* Wv[2] = {0, 0};
    const float* bv[2] = {0, 0};
    int wi = 0, bi = 0;
    for (int i = 0; i < n_in; i++) {
        int sz = in_sizes[i];
        if (sz == NN * DD)      feats = (const float*)d_in[i];
        else if (sz == NE)      { if (!edgeA) edgeA = (const int*)d_in[i]; else edgeB = (const int*)d_in[i]; }
        else if (sz == DD * DD) { if (wi < 2) Wv[wi++] = (const float*)d_in[i]; }
        else if (sz == DD)      { if (bi < 2) bv[bi++] = (const float*)d_in[i]; }
    }
    const int* src = edgeA;   // insertion order: src precedes dst (verified R4)
    const int* dst = edgeB;
    float* out = (float*)d_out;

    const int T = 256;
    const int g_nodes  = (NN + T - 1) / T;
    const int g_edges4 = (NE / 4 + T - 1) / T;
    const int g_scale  = (NN * 8 + T - 1) / T;   // 2 float4 per thread
    const int g_vec    = (NN * 16 + T - 1) / T;

    k_zero <<<g_nodes,  T>>>();
    k_build<<<g_edges4, T>>>((const int4*)src, (const int4*)dst);
    k_scale<<<g_scale,  T>>>((const float4*)feats);   // also writes norms

    k_agg<1>     <<<g_vec, T>>>(src, dst);
    k_gemm_mma<1><<<NTM, 128>>>(Wv[0], bv[0], 0);

    k_agg<2>     <<<g_vec, T>>>(src, dst);
    k_gemm_mma<2><<<NTM, 128>>>(Wv[1], bv[1], out);
}

// round 10
// speedup vs baseline: 1.0751x; 1.0751x over previous
#include <cuda_runtime.h>
#include <cuda_fp16.h>

#define NN 100000
#define NE 1200000
#define DD 64
#define ADJ_STRIDE 32
#define OVF_CAP 8192
#define NTM 782                 // ceil(100000/128) GEMM tiles
#define SW128(o) ((o) ^ ((((o) >> 3)) & 0x70))

typedef unsigned long long u64;

// Scratch (device globals — no allocation allowed)
__device__ __half g_Hh  [NN * DD];        // layer-1 gather source (feats*nout)
__device__ __half g_H2h [NN * DD];        // layer-2 gather source
__device__ __half g_AGGh[NN * DD];        // gather output = GEMM A operand
__device__ int   g_degout[NN];
__device__ int   g_cnt[NN];
__device__ float g_nout[NN];
__device__ float g_nin[NN];
__device__ int   g_adj[NN * ADJ_STRIDE];
__device__ int   g_ovf[OVF_CAP];
__device__ int   g_ovf_cnt;

// ---------------------------------------------------------------------------
__global__ void k_zero() {
    int i = blockIdx.x * blockDim.x + threadIdx.x;
    if (i < NN) { g_degout[i] = 0; g_cnt[i] = 0; }
    if (i == 0) g_ovf_cnt = 0;
}

// 4 edges per thread (int4 loads) for atomic-latency MLP.
__global__ void k_build(const int4* __restrict__ src4, const int4* __restrict__ dst4) {
    int e4 = blockIdx.x * blockDim.x + threadIdx.x;
    if (e4 >= NE / 4) return;
    int4 s = src4[e4];
    int4 d = dst4[e4];
    atomicAdd(&g_degout[s.x], 1);
    atomicAdd(&g_degout[s.y], 1);
    atomicAdd(&g_degout[s.z], 1);
    atomicAdd(&g_degout[s.w], 1);
    int c0 = atomicAdd(&g_cnt[d.x], 1);
    int c1 = atomicAdd(&g_cnt[d.y], 1);
    int c2 = atomicAdd(&g_cnt[d.z], 1);
    int c3 = atomicAdd(&g_cnt[d.w], 1);
    int base = e4 * 4;
    if (c0 < ADJ_STRIDE) g_adj[d.x * ADJ_STRIDE + c0] = s.x;
    else { int o = atomicAdd(&g_ovf_cnt, 1); if (o < OVF_CAP) g_ovf[o] = base; }
    if (c1 < ADJ_STRIDE) g_adj[d.y * ADJ_STRIDE + c1] = s.y;
    else { int o = atomicAdd(&g_ovf_cnt, 1); if (o < OVF_CAP) g_ovf[o] = base + 1; }
    if (c2 < ADJ_STRIDE) g_adj[d.z * ADJ_STRIDE + c2] = s.z;
    else { int o = atomicAdd(&g_ovf_cnt, 1); if (o < OVF_CAP) g_ovf[o] = base + 2; }
    if (c3 < ADJ_STRIDE) g_adj[d.w * ADJ_STRIDE + c3] = s.w;
    else { int o = atomicAdd(&g_ovf_cnt, 1); if (o < OVF_CAP) g_ovf[o] = base + 3; }
}

// Fused norm + scale: Hh = half(feats * nout[row]); persists norms (lane 0).
__global__ void k_scale(const float4* __restrict__ feats) {
    int t = blockIdx.x * blockDim.x + threadIdx.x;
    if (t >= NN * 16) return;
    int row = t >> 4;
    float s = rsqrtf(fmaxf((float)g_degout[row], 1.0f));
    if ((t & 15) == 0) {
        g_nout[row] = s;
        g_nin[row] = rsqrtf(fmaxf((float)g_cnt[row], 1.0f));
    }
    float4 v = feats[t];
    __half2 h0 = __floats2half2_rn(v.x * s, v.y * s);
    __half2 h1 = __floats2half2_rn(v.z * s, v.w * s);
    uint2 u;
    u.x = *reinterpret_cast<unsigned*>(&h0);
    u.y = *reinterpret_cast<unsigned*>(&h1);
    reinterpret_cast<uint2*>(g_Hh)[t] = u;
}

// acc (8 floats) += 8 halves packed in uint4
__device__ __forceinline__ void acc8h(float4& a, float4& b, uint4 u) {
    float2 f0 = __half22float2(*reinterpret_cast<__half2*>(&u.x));
    float2 f1 = __half22float2(*reinterpret_cast<__half2*>(&u.y));
    float2 f2 = __half22float2(*reinterpret_cast<__half2*>(&u.z));
    float2 f3 = __half22float2(*reinterpret_cast<__half2*>(&u.w));
    a.x += f0.x; a.y += f0.y; a.z += f1.x; a.w += f1.y;
    b.x += f2.x; b.y += f2.y; b.z += f3.x; b.w += f3.y;
}
// pairwise fp16 add of two uint4s (4x HADD2)
__device__ __forceinline__ uint4 hadd2x4(uint4 a, uint4 b) {
    uint4 r;
    *reinterpret_cast<__half2*>(&r.x) = __hadd2(*reinterpret_cast<__half2*>(&a.x),
                                                *reinterpret_cast<__half2*>(&b.x));
    *reinterpret_cast<__half2*>(&r.y) = __hadd2(*reinterpret_cast<__half2*>(&a.y),
                                                *reinterpret_cast<__half2*>(&b.y));
    *reinterpret_cast<__half2*>(&r.z) = __hadd2(*reinterpret_cast<__half2*>(&a.z),
                                                *reinterpret_cast<__half2*>(&b.z));
    *reinterpret_cast<__half2*>(&r.w) = __hadd2(*reinterpret_cast<__half2*>(&a.w),
                                                *reinterpret_cast<__half2*>(&b.w));
    return r;
}

// Gather: AGGh[n] = half( (sum_{s in adj[n]} H[s]) * nin[n] )
// NN*8 threads: thread j of node n owns uint4 chunk j (8 halves, 16B).
// Edges processed in pairs: fp16 HADD2 pair-sum, then fp32 accumulate.
template <int LAYER>
__global__ void __launch_bounds__(256) k_agg(const int* __restrict__ src,
                                             const int* __restrict__ dst) {
    int t = blockIdx.x * blockDim.x + threadIdx.x;
    if (t >= NN * 8) return;
    int n = t >> 3, j = t & 7;
    const uint4* Hv = reinterpret_cast<const uint4*>(LAYER == 1 ? g_Hh : g_H2h);
    int cnt = g_cnt[n];
    int lim = cnt < ADJ_STRIDE ? cnt : ADJ_STRIDE;
    const int* lst = &g_adj[n * ADJ_STRIDE];
    float4 accA = make_float4(0.f, 0.f, 0.f, 0.f);
    float4 accB = make_float4(0.f, 0.f, 0.f, 0.f);
    int k = 0;
    for (; k + 4 <= lim; k += 4) {
        int4 s4 = *reinterpret_cast<const int4*>(&lst[k]);
        uint4 u0 = Hv[s4.x * 8 + j];
        uint4 u1 = Hv[s4.y * 8 + j];
        uint4 u2 = Hv[s4.z * 8 + j];
        uint4 u3 = Hv[s4.w * 8 + j];
        acc8h(accA, accB, hadd2x4(u0, u1));
        acc8h(accA, accB, hadd2x4(u2, u3));
    }
    for (; k + 2 <= lim; k += 2) {
        uint4 u0 = Hv[__ldg(&lst[k]) * 8 + j];
        uint4 u1 = Hv[__ldg(&lst[k + 1]) * 8 + j];
        acc8h(accA, accB, hadd2x4(u0, u1));
    }
    if (k < lim) acc8h(accA, accB, Hv[__ldg(&lst[k]) * 8 + j]);
    if (cnt > ADJ_STRIDE) {                 // overflow (expected none)
        int oc = g_ovf_cnt; if (oc > OVF_CAP) oc = OVF_CAP;
        for (int i = 0; i < oc; i++) {
            int e = g_ovf[i];
            if (dst[e] == n) acc8h(accA, accB, Hv[src[e] * 8 + j]);
        }
    }
    float s = g_nin[n];
    __half2 h0 = __floats2half2_rn(accA.x * s, accA.y * s);
    __half2 h1 = __floats2half2_rn(accA.z * s, accA.w * s);
    __half2 h2 = __floats2half2_rn(accB.x * s, accB.y * s);
    __half2 h3 = __floats2half2_rn(accB.z * s, accB.w * s);
    uint4 u;
    u.x = *reinterpret_cast<unsigned*>(&h0);
    u.y = *reinterpret_cast<unsigned*>(&h1);
    u.z = *reinterpret_cast<unsigned*>(&h2);
    u.w = *reinterpret_cast<unsigned*>(&h3);
    reinterpret_cast<uint4*>(g_AGGh)[t] = u;
}

// ---------------------------------------------------------------------------
// Warp-MMA GEMM (HMMA): D(128x64) = A(128x64) @ W(64x64)
__device__ __forceinline__ unsigned smem_u32(const void* p) {
    unsigned a;
    asm("{ .reg .u64 t; cvta.to.shared.u64 t, %1; cvt.u32.u64 %0, t; }" : "=r"(a) : "l"(p));
    return a;
}
__device__ __forceinline__ void ldmx4(unsigned& r0, unsigned& r1, unsigned& r2,
                                      unsigned& r3, unsigned addr) {
    asm volatile("ldmatrix.sync.aligned.m8n8.x4.shared.b16 {%0,%1,%2,%3}, [%4];"
                 : "=r"(r0), "=r"(r1), "=r"(r2), "=r"(r3) : "r"(addr));
}
__device__ __forceinline__ void mma16816(float* d, unsigned a0, unsigned a1,
                                         unsigned a2, unsigned a3,
                                         unsigned b0, unsigned b1) {
    asm volatile(
        "mma.sync.aligned.m16n8k16.row.col.f32.f16.f16.f32 "
        "{%0,%1,%2,%3}, {%4,%5,%6,%7}, {%8,%9}, {%0,%1,%2,%3};"
        : "+f"(d[0]), "+f"(d[1]), "+f"(d[2]), "+f"(d[3])
        : "r"(a0), "r"(a1), "r"(a2), "r"(a3), "r"(b0), "r"(b1));
}

template <int LAYER>
__global__ void __launch_bounds__(128)
k_gemm_mma(const float* __restrict__ W, const float* __restrict__ bias,
           float* __restrict__ out_param) {
    __shared__ __align__(16) __half sA[128 * 64];
    __shared__ __align__(16) __half sB[64 * 64];
    __shared__ float bs[64];

    const int t = threadIdx.x;
    const int wid = t >> 5, lane = t & 31;

    for (int i = t; i < 4096; i += 128) {
        int k = i >> 6, c = i & 63;
        *reinterpret_cast<__half*>(
            reinterpret_cast<char*>(sB) + SW128(c * 128 + k * 2)) = __float2half_rn(W[i]);
    }
    if (t < 64) bs[t] = bias[t];

    int gr = blockIdx.x * 128 + t;
    {
        const uint4* a4 = reinterpret_cast<const uint4*>(g_AGGh);
        #pragma unroll
        for (int ch = 0; ch < 8; ch++) {
            uint4 v = make_uint4(0u, 0u, 0u, 0u);
            if (gr < NN) v = a4[gr * 8 + ch];
            *reinterpret_cast<uint4*>(
                reinterpret_cast<char*>(sA) + SW128(t * 128 + ch * 16)) = v;
        }
    }
    __syncthreads();

    const unsigned baseA = smem_u32(sA);
    const unsigned baseB = smem_u32(sB);
    const int lrow = lane & 15;
    const int lcol = (lane >> 4) * 16;

    float d[2][8][4];
    #pragma unroll
    for (int i = 0; i < 2; i++)
        #pragma unroll
        for (int j = 0; j < 8; j++)
            #pragma unroll
            for (int q = 0; q < 4; q++) d[i][j][q] = 0.f;

    #pragma unroll
    for (int kk = 0; kk < 4; kk++) {
        unsigned a[2][4];
        #pragma unroll
        for (int i = 0; i < 2; i++) {
            int row = wid * 32 + i * 16 + lrow;
            unsigned addr = baseA + SW128(row * 128 + kk * 32 + lcol);
            ldmx4(a[i][0], a[i][1], a[i][2], a[i][3], addr);
        }
        #pragma unroll
        for (int p = 0; p < 4; p++) {
            unsigned r0, r1, r2, r3;
            int nrow = p * 16 + lrow;
            unsigned addr = baseB + SW128(nrow * 128 + kk * 32 + lcol);
            ldmx4(r0, r1, r2, r3, addr);
            #pragma unroll
            for (int i = 0; i < 2; i++) {
                mma16816(d[i][p * 2 + 0], a[i][0], a[i][1], a[i][2], a[i][3], r0, r2);
                mma16816(d[i][p * 2 + 1], a[i][0], a[i][1], a[i][2], a[i][3], r1, r3);
            }
        }
    }

    const int g   = lane >> 2;
    const int tid = lane & 3;
    #pragma unroll
    for (int i = 0; i < 2; i++) {
        #pragma unroll
        for (int half = 0; half < 2; half++) {
            int row = blockIdx.x * 128 + wid * 32 + i * 16 + g + half * 8;
            if (row >= NN) continue;
            float no = (LAYER == 1) ? g_nout[row] : 0.f;
            #pragma unroll
            for (int j = 0; j < 8; j++) {
                int c = j * 8 + tid * 2;
                float v0 = d[i][j][half * 2 + 0] + bs[c];
                float v1 = d[i][j][half * 2 + 1] + bs[c + 1];
                if (LAYER == 1) {
                    v0 = fmaxf(v0, 0.f) * no;
                    v1 = fmaxf(v1, 0.f) * no;
                    __half2 h = __floats2half2_rn(v0, v1);
                    *reinterpret_cast<__half2*>(&g_H2h[row * DD + c]) = h;
                } else {
                    *reinterpret_cast<float2*>(&out_param[row * DD + c]) =
                        make_float2(v0, v1);
                }
            }
        }
    }
}

// ---------------------------------------------------------------------------
extern "C" void kernel_launch(void* const* d_in, const int* in_sizes, int n_in,
                              void* d_out, int out_size) {
    const float* feats = 0;
    const int *edgeA = 0, *edgeB = 0;
    const float* Wv[2] = {0, 0};
    const float* bv[2] = {0, 0};
    int wi = 0, bi = 0;
    for (int i = 0; i < n_in; i++) {
        int sz = in_sizes[i];
        if (sz == NN * DD)      feats = (const float*)d_in[i];
        else if (sz == NE)      { if (!edgeA) edgeA = (const int*)d_in[i]; else edgeB = (const int*)d_in[i]; }
        else if (sz == DD * DD) { if (wi < 2) Wv[wi++] = (const float*)d_in[i]; }
        else if (sz == DD)      { if (bi < 2) bv[bi++] = (const float*)d_in[i]; }
    }
    const int* src = edgeA;   // insertion order: src precedes dst (verified R4)
    const int* dst = edgeB;
    float* out = (float*)d_out;

    const int T = 256;
    const int g_nodes  = (NN + T - 1) / T;
    const int g_edges4 = (NE / 4 + T - 1) / T;
    const int g_vec    = (NN * 16 + T - 1) / T;   // k_scale
    const int g_agg    = (NN * 8 + T - 1) / T;    // k_agg (uint4 lanes)

    k_zero <<<g_nodes,  T>>>();
    k_build<<<g_edges4, T>>>((const int4*)src, (const int4*)dst);
    k_scale<<<g_vec,    T>>>((const float4*)feats);   // also writes norms

    k_agg<1>     <<<g_agg, T>>>(src, dst);
    k_gemm_mma<1><<<NTM, 128>>>(Wv[0], bv[0], 0);

    k_agg<2>     <<<g_agg, T>>>(src, dst);
    k_gemm_mma<2><<<NTM, 128>>>(Wv[1], bv[1], out);
}

// round 11
// speedup vs baseline: 1.0775x; 1.0022x over previous
#include <cuda_runtime.h>
#include <cuda_fp16.h>

#define NN 100000
#define NE 1200000
#define DD 64
#define ADJ_STRIDE 32
#define OVF_CAP 8192
#define NTM 782                 // ceil(100000/128) GEMM tiles
#define SW128(o) ((o) ^ ((((o) >> 3)) & 0x70))

typedef unsigned long long u64;

// Scratch (device globals — no allocation allowed)
__device__ __half g_Hh  [NN * DD];        // layer-1 gather source (feats*nout)
__device__ __half g_H2h [NN * DD];        // layer-2 gather source
__device__ __half g_AGGh[NN * DD];        // gather output = GEMM A operand
__device__ __half g_Wt[2][DD * DD];       // pre-transposed fp16 weights [c*64+k]
__device__ int   g_degout[NN];
__device__ int   g_cnt[NN];
__device__ float g_nout[NN];
__device__ float g_nin[NN];
__device__ int   g_adj[NN * ADJ_STRIDE];
__device__ int   g_ovf[OVF_CAP];
__device__ int   g_ovf_cnt;

// ---------------------------------------------------------------------------
__global__ void k_zero() {
    int i = blockIdx.x * blockDim.x + threadIdx.x;
    if (i < NN) { g_degout[i] = 0; g_cnt[i] = 0; }
    if (i == 0) g_ovf_cnt = 0;
}

// Pre-transpose both weight matrices to fp16: g_Wt[l][c*64+k] = W_l[k*64+c]
__global__ void k_prep(const float* __restrict__ W1, const float* __restrict__ W2) {
    int i = blockIdx.x * blockDim.x + threadIdx.x;   // 8192 threads
    if (i >= 2 * DD * DD) return;
    int l = i >> 12;
    int r = i & 4095;
    int c = r >> 6, k = r & 63;
    const float* W = l ? W2 : W1;
    g_Wt[l][c * 64 + k] = __float2half_rn(W[k * 64 + c]);
}

// 4 edges per thread (int4 loads) for atomic-latency MLP.
__global__ void k_build(const int4* __restrict__ src4, const int4* __restrict__ dst4) {
    int e4 = blockIdx.x * blockDim.x + threadIdx.x;
    if (e4 >= NE / 4) return;
    int4 s = src4[e4];
    int4 d = dst4[e4];
    atomicAdd(&g_degout[s.x], 1);
    atomicAdd(&g_degout[s.y], 1);
    atomicAdd(&g_degout[s.z], 1);
    atomicAdd(&g_degout[s.w], 1);
    int c0 = atomicAdd(&g_cnt[d.x], 1);
    int c1 = atomicAdd(&g_cnt[d.y], 1);
    int c2 = atomicAdd(&g_cnt[d.z], 1);
    int c3 = atomicAdd(&g_cnt[d.w], 1);
    int base = e4 * 4;
    if (c0 < ADJ_STRIDE) g_adj[d.x * ADJ_STRIDE + c0] = s.x;
    else { int o = atomicAdd(&g_ovf_cnt, 1); if (o < OVF_CAP) g_ovf[o] = base; }
    if (c1 < ADJ_STRIDE) g_adj[d.y * ADJ_STRIDE + c1] = s.y;
    else { int o = atomicAdd(&g_ovf_cnt, 1); if (o < OVF_CAP) g_ovf[o] = base + 1; }
    if (c2 < ADJ_STRIDE) g_adj[d.z * ADJ_STRIDE + c2] = s.z;
    else { int o = atomicAdd(&g_ovf_cnt, 1); if (o < OVF_CAP) g_ovf[o] = base + 2; }
    if (c3 < ADJ_STRIDE) g_adj[d.w * ADJ_STRIDE + c3] = s.w;
    else { int o = atomicAdd(&g_ovf_cnt, 1); if (o < OVF_CAP) g_ovf[o] = base + 3; }
}

// Fused norm + scale: Hh = half(feats * nout[row]); persists norms (lane 0).
__global__ void k_scale(const float4* __restrict__ feats) {
    int t = blockIdx.x * blockDim.x + threadIdx.x;
    if (t >= NN * 16) return;
    int row = t >> 4;
    float s = rsqrtf(fmaxf((float)g_degout[row], 1.0f));
    if ((t & 15) == 0) {
        g_nout[row] = s;
        g_nin[row] = rsqrtf(fmaxf((float)g_cnt[row], 1.0f));
    }
    float4 v = feats[t];
    __half2 h0 = __floats2half2_rn(v.x * s, v.y * s);
    __half2 h1 = __floats2half2_rn(v.z * s, v.w * s);
    uint2 u;
    u.x = *reinterpret_cast<unsigned*>(&h0);
    u.y = *reinterpret_cast<unsigned*>(&h1);
    reinterpret_cast<uint2*>(g_Hh)[t] = u;
}

// acc (8 floats) += 8 halves packed in uint4
__device__ __forceinline__ void acc8h(float4& a, float4& b, uint4 u) {
    float2 f0 = __half22float2(*reinterpret_cast<__half2*>(&u.x));
    float2 f1 = __half22float2(*reinterpret_cast<__half2*>(&u.y));
    float2 f2 = __half22float2(*reinterpret_cast<__half2*>(&u.z));
    float2 f3 = __half22float2(*reinterpret_cast<__half2*>(&u.w));
    a.x += f0.x; a.y += f0.y; a.z += f1.x; a.w += f1.y;
    b.x += f2.x; b.y += f2.y; b.z += f3.x; b.w += f3.y;
}
// pairwise fp16 add of two uint4s (4x HADD2)
__device__ __forceinline__ uint4 hadd2x4(uint4 a, uint4 b) {
    uint4 r;
    *reinterpret_cast<__half2*>(&r.x) = __hadd2(*reinterpret_cast<__half2*>(&a.x),
                                                *reinterpret_cast<__half2*>(&b.x));
    *reinterpret_cast<__half2*>(&r.y) = __hadd2(*reinterpret_cast<__half2*>(&a.y),
                                                *reinterpret_cast<__half2*>(&b.y));
    *reinterpret_cast<__half2*>(&r.z) = __hadd2(*reinterpret_cast<__half2*>(&a.z),
                                                *reinterpret_cast<__half2*>(&b.z));
    *reinterpret_cast<__half2*>(&r.w) = __hadd2(*reinterpret_cast<__half2*>(&a.w),
                                                *reinterpret_cast<__half2*>(&b.w));
    return r;
}

// Gather: AGGh[n] = half( (sum_{s in adj[n]} H[s]) * nin[n] )
// NN*8 threads: thread j of node n owns uint4 chunk j (8 halves, 16B).
// 8 edges in flight per iteration; depth-1 fp16 pair-sum then fp32 accumulate.
template <int LAYER>
__global__ void __launch_bounds__(256) k_agg(const int* __restrict__ src,
                                             const int* __restrict__ dst) {
    int t = blockIdx.x * blockDim.x + threadIdx.x;
    if (t >= NN * 8) return;
    int n = t >> 3, j = t & 7;
    const uint4* Hv = reinterpret_cast<const uint4*>(LAYER == 1 ? g_Hh : g_H2h);
    int cnt = g_cnt[n];
    int lim = cnt < ADJ_STRIDE ? cnt : ADJ_STRIDE;
    const int* lst = &g_adj[n * ADJ_STRIDE];
    float4 accA = make_float4(0.f, 0.f, 0.f, 0.f);
    float4 accB = make_float4(0.f, 0.f, 0.f, 0.f);
    int k = 0;
    for (; k + 8 <= lim; k += 8) {
        int4 p4 = *reinterpret_cast<const int4*>(&lst[k]);
        int4 q4 = *reinterpret_cast<const int4*>(&lst[k + 4]);
        uint4 u0 = Hv[p4.x * 8 + j];
        uint4 u1 = Hv[p4.y * 8 + j];
        uint4 u2 = Hv[p4.z * 8 + j];
        uint4 u3 = Hv[p4.w * 8 + j];
        uint4 u4 = Hv[q4.x * 8 + j];
        uint4 u5 = Hv[q4.y * 8 + j];
        uint4 u6 = Hv[q4.z * 8 + j];
        uint4 u7 = Hv[q4.w * 8 + j];
        acc8h(accA, accB, hadd2x4(u0, u1));
        acc8h(accA, accB, hadd2x4(u2, u3));
        acc8h(accA, accB, hadd2x4(u4, u5));
        acc8h(accA, accB, hadd2x4(u6, u7));
    }
    for (; k + 4 <= lim; k += 4) {
        int4 s4 = *reinterpret_cast<const int4*>(&lst[k]);
        uint4 u0 = Hv[s4.x * 8 + j];
        uint4 u1 = Hv[s4.y * 8 + j];
        uint4 u2 = Hv[s4.z * 8 + j];
        uint4 u3 = Hv[s4.w * 8 + j];
        acc8h(accA, accB, hadd2x4(u0, u1));
        acc8h(accA, accB, hadd2x4(u2, u3));
    }
    for (; k + 2 <= lim; k += 2) {
        uint4 u0 = Hv[__ldg(&lst[k]) * 8 + j];
        uint4 u1 = Hv[__ldg(&lst[k + 1]) * 8 + j];
        acc8h(accA, accB, hadd2x4(u0, u1));
    }
    if (k < lim) acc8h(accA, accB, Hv[__ldg(&lst[k]) * 8 + j]);
    if (cnt > ADJ_STRIDE) {                 // overflow (expected none)
        int oc = g_ovf_cnt; if (oc > OVF_CAP) oc = OVF_CAP;
        for (int i = 0; i < oc; i++) {
            int e = g_ovf[i];
            if (dst[e] == n) acc8h(accA, accB, Hv[src[e] * 8 + j]);
        }
    }
    float s = g_nin[n];
    __half2 h0 = __floats2half2_rn(accA.x * s, accA.y * s);
    __half2 h1 = __floats2half2_rn(accA.z * s, accA.w * s);
    __half2 h2 = __floats2half2_rn(accB.x * s, accB.y * s);
    __half2 h3 = __floats2half2_rn(accB.z * s, accB.w * s);
    uint4 u;
    u.x = *reinterpret_cast<unsigned*>(&h0);
    u.y = *reinterpret_cast<unsigned*>(&h1);
    u.z = *reinterpret_cast<unsigned*>(&h2);
    u.w = *reinterpret_cast<unsigned*>(&h3);
    reinterpret_cast<uint4*>(g_AGGh)[t] = u;
}

// ---------------------------------------------------------------------------
// Warp-MMA GEMM (HMMA): D(128x64) = A(128x64) @ W(64x64)
__device__ __forceinline__ unsigned smem_u32(const void* p) {
    unsigned a;
    asm("{ .reg .u64 t; cvta.to.shared.u64 t, %1; cvt.u32.u64 %0, t; }" : "=r"(a) : "l"(p));
    return a;
}
__device__ __forceinline__ void ldmx4(unsigned& r0, unsigned& r1, unsigned& r2,
                                      unsigned& r3, unsigned addr) {
    asm volatile("ldmatrix.sync.aligned.m8n8.x4.shared.b16 {%0,%1,%2,%3}, [%4];"
                 : "=r"(r0), "=r"(r1), "=r"(r2), "=r"(r3) : "r"(addr));
}
__device__ __forceinline__ void mma16816(float* d, unsigned a0, unsigned a1,
                                         unsigned a2, unsigned a3,
                                         unsigned b0, unsigned b1) {
    asm volatile(
        "mma.sync.aligned.m16n8k16.row.col.f32.f16.f16.f32 "
        "{%0,%1,%2,%3}, {%4,%5,%6,%7}, {%8,%9}, {%0,%1,%2,%3};"
        : "+f"(d[0]), "+f"(d[1]), "+f"(d[2]), "+f"(d[3])
        : "r"(a0), "r"(a1), "r"(a2), "r"(a3), "r"(b0), "r"(b1));
}

template <int LAYER>
__global__ void __launch_bounds__(128)
k_gemm_mma(const float* __restrict__ bias, float* __restrict__ out_param) {
    __shared__ __align__(16) __half sA[128 * 64];
    __shared__ __align__(16) __half sB[64 * 64];
    __shared__ float bs[64];

    const int t = threadIdx.x;
    const int wid = t >> 5, lane = t & 31;

    // B: pre-transposed fp16 weights -> vectorized swizzled copy (4x16B/thread)
    {
        const uint4* wt4 = reinterpret_cast<const uint4*>(g_Wt[LAYER - 1]);
        #pragma unroll
        for (int q = 0; q < 4; q++) {
            int idx = q * 128 + t;               // uint4 index; row c = idx>>3
            uint4 v = wt4[idx];
            *reinterpret_cast<uint4*>(
                reinterpret_cast<char*>(sB) + SW128(idx * 16)) = v;
        }
    }
    if (t < 64) bs[t] = bias[t];

    int gr = blockIdx.x * 128 + t;
    {
        const uint4* a4 = reinterpret_cast<const uint4*>(g_AGGh);
        #pragma unroll
        for (int ch = 0; ch < 8; ch++) {
            uint4 v = make_uint4(0u, 0u, 0u, 0u);
            if (gr < NN) v = a4[gr * 8 + ch];
            *reinterpret_cast<uint4*>(
                reinterpret_cast<char*>(sA) + SW128(t * 128 + ch * 16)) = v;
        }
    }
    __syncthreads();

    const unsigned baseA = smem_u32(sA);
    const unsigned baseB = smem_u32(sB);
    const int lrow = lane & 15;
    const int lcol = (lane >> 4) * 16;

    float d[2][8][4];
    #pragma unroll
    for (int i = 0; i < 2; i++)
        #pragma unroll
        for (int j = 0; j < 8; j++)
            #pragma unroll
            for (int q = 0; q < 4; q++) d[i][j][q] = 0.f;

    #pragma unroll
    for (int kk = 0; kk < 4; kk++) {
        unsigned a[2][4];
        #pragma unroll
        for (int i = 0; i < 2; i++) {
            int row = wid * 32 + i * 16 + lrow;
            unsigned addr = baseA + SW128(row * 128 + kk * 32 + lcol);
            ldmx4(a[i][0], a[i][1], a[i][2], a[i][3], addr);
        }
        #pragma unroll
        for (int p = 0; p < 4; p++) {
            unsigned r0, r1, r2, r3;
            int nrow = p * 16 + lrow;
            unsigned addr = baseB + SW128(nrow * 128 + kk * 32 + lcol);
            ldmx4(r0, r1, r2, r3, addr);
            #pragma unroll
            for (int i = 0; i < 2; i++) {
                mma16816(d[i][p * 2 + 0], a[i][0], a[i][1], a[i][2], a[i][3], r0, r2);
                mma16816(d[i][p * 2 + 1], a[i][0], a[i][1], a[i][2], a[i][3], r1, r3);
            }
        }
    }

    const int g   = lane >> 2;
    const int tid = lane & 3;
    #pragma unroll
    for (int i = 0; i < 2; i++) {
        #pragma unroll
        for (int half = 0; half < 2; half++) {
            int row = blockIdx.x * 128 + wid * 32 + i * 16 + g + half * 8;
            if (row >= NN) continue;
            float no = (LAYER == 1) ? g_nout[row] : 0.f;
            #pragma unroll
            for (int j = 0; j < 8; j++) {
                int c = j * 8 + tid * 2;
                float v0 = d[i][j][half * 2 + 0] + bs[c];
                float v1 = d[i][j][half * 2 + 1] + bs[c + 1];
                if (LAYER == 1) {
                    v0 = fmaxf(v0, 0.f) * no;
                    v1 = fmaxf(v1, 0.f) * no;
                    __half2 h = __floats2half2_rn(v0, v1);
                    *reinterpret_cast<__half2*>(&g_H2h[row * DD + c]) = h;
                } else {
                    *reinterpret_cast<float2*>(&out_param[row * DD + c]) =
                        make_float2(v0, v1);
                }
            }
        }
    }
}

// ---------------------------------------------------------------------------
extern "C" void kernel_launch(void* const* d_in, const int* in_sizes, int n_in,
                              void* d_out, int out_size) {
    const float* feats = 0;
    const int *edgeA = 0, *edgeB = 0;
    const float* Wv[2] = {0, 0};
    const float* bv[2] = {0, 0};
    int wi = 0, bi = 0;
    for (int i = 0; i < n_in; i++) {
        int sz = in_sizes[i];
        if (sz == NN * DD)      feats = (const float*)d_in[i];
        else if (sz == NE)      { if (!edgeA) edgeA = (const int*)d_in[i]; else edgeB = (const int*)d_in[i]; }
        else if (sz == DD * DD) { if (wi < 2) Wv[wi++] = (const float*)d_in[i]; }
        else if (sz == DD)      { if (bi < 2) bv[bi++] = (const float*)d_in[i]; }
    }
    const int* src = edgeA;   // insertion order: src precedes dst (verified R4)
    const int* dst = edgeB;
    float* out = (float*)d_out;

    const int T = 256;
    const int g_nodes  = (NN + T - 1) / T;
    const int g_edges4 = (NE / 4 + T - 1) / T;
    const int g_vec    = (NN * 16 + T - 1) / T;   // k_scale
    const int g_agg    = (NN * 8 + T - 1) / T;    // k_agg (uint4 lanes)

    k_zero <<<g_nodes,  T>>>();
    k_prep <<<32,       T>>>(Wv[0], Wv[1]);
    k_build<<<g_edges4, T>>>((const int4*)src, (const int4*)dst);
    k_scale<<<g_vec,    T>>>((const float4*)feats);   // also writes norms

    k_agg<1>     <<<g_agg, T>>>(src, dst);
    k_gemm_mma<1><<<NTM, 128>>>(bv[0], 0);

    k_agg<2>     <<<g_agg, T>>>(src, dst);
    k_gemm_mma<2><<<NTM, 128>>>(bv[1], out);
}

// round 12
// speedup vs baseline: 1.1761x; 1.0915x over previous
#include <cuda_runtime.h>
#include <cuda_fp16.h>

#define NN 100000
#define NE 1200000
#define DD 64
#define ADJ_STRIDE 32
#define OVF_CAP 8192
#define NTM 782                 // ceil(100000/128) GEMM tiles
#define SW128(o) ((o) ^ ((((o) >> 3)) & 0x70))

typedef unsigned long long u64;

// Scratch (device globals — no allocation allowed)
__device__ __half g_Hh  [NN * DD];        // layer-1 gather source (feats*nout)
__device__ __half g_H2h [NN * DD];        // layer-2 gather source
__device__ __half g_AGGh[NN * DD];        // gather output = GEMM A operand
__device__ __half g_Wt[2][DD * DD];       // pre-transposed fp16 weights [c*64+k]
__device__ int   g_degout[NN];
__device__ int   g_cnt[NN];
__device__ float g_nout[NN];
__device__ float g_nin[NN];
__device__ int   g_adj[NN * ADJ_STRIDE];
__device__ int   g_ovf[OVF_CAP];
__device__ int   g_ovf_cnt;

// ---------------------------------------------------------------------------
// zero counters + pre-transpose weights (merged: saves a launch)
__global__ void k_zero(const float* __restrict__ W1, const float* __restrict__ W2) {
    int i = blockIdx.x * blockDim.x + threadIdx.x;
    if (i < NN) { g_degout[i] = 0; g_cnt[i] = 0; }
    if (i == 0) g_ovf_cnt = 0;
    if (i < 2 * DD * DD) {
        int l = i >> 12;
        int r = i & 4095;
        int c = r >> 6, k = r & 63;
        const float* W = l ? W2 : W1;
        g_Wt[l][c * 64 + k] = __float2half_rn(W[k * 64 + c]);
    }
}

// 4 edges per thread (int4 loads) for atomic-latency MLP.
__global__ void k_build(const int4* __restrict__ src4, const int4* __restrict__ dst4) {
    int e4 = blockIdx.x * blockDim.x + threadIdx.x;
    if (e4 >= NE / 4) return;
    int4 s = src4[e4];
    int4 d = dst4[e4];
    atomicAdd(&g_degout[s.x], 1);
    atomicAdd(&g_degout[s.y], 1);
    atomicAdd(&g_degout[s.z], 1);
    atomicAdd(&g_degout[s.w], 1);
    int c0 = atomicAdd(&g_cnt[d.x], 1);
    int c1 = atomicAdd(&g_cnt[d.y], 1);
    int c2 = atomicAdd(&g_cnt[d.z], 1);
    int c3 = atomicAdd(&g_cnt[d.w], 1);
    int base = e4 * 4;
    if (c0 < ADJ_STRIDE) g_adj[d.x * ADJ_STRIDE + c0] = s.x;
    else { int o = atomicAdd(&g_ovf_cnt, 1); if (o < OVF_CAP) g_ovf[o] = base; }
    if (c1 < ADJ_STRIDE) g_adj[d.y * ADJ_STRIDE + c1] = s.y;
    else { int o = atomicAdd(&g_ovf_cnt, 1); if (o < OVF_CAP) g_ovf[o] = base + 1; }
    if (c2 < ADJ_STRIDE) g_adj[d.z * ADJ_STRIDE + c2] = s.z;
    else { int o = atomicAdd(&g_ovf_cnt, 1); if (o < OVF_CAP) g_ovf[o] = base + 2; }
    if (c3 < ADJ_STRIDE) g_adj[d.w * ADJ_STRIDE + c3] = s.w;
    else { int o = atomicAdd(&g_ovf_cnt, 1); if (o < OVF_CAP) g_ovf[o] = base + 3; }
}

// norms from final counts (tiny)
__global__ void k_norm() {
    int i = blockIdx.x * blockDim.x + threadIdx.x;
    if (i < NN) {
        g_nout[i] = rsqrtf(fmaxf((float)g_degout[i], 1.0f));
        g_nin[i]  = rsqrtf(fmaxf((float)g_cnt[i],  1.0f));
    }
}

// Pure stream: Hh = half(feats * nout[row])
__global__ void k_scale(const float4* __restrict__ feats) {
    int t = blockIdx.x * blockDim.x + threadIdx.x;
    if (t >= NN * 16) return;
    float s = g_nout[t >> 4];
    float4 v = feats[t];
    __half2 h0 = __floats2half2_rn(v.x * s, v.y * s);
    __half2 h1 = __floats2half2_rn(v.z * s, v.w * s);
    uint2 u;
    u.x = *reinterpret_cast<unsigned*>(&h0);
    u.y = *reinterpret_cast<unsigned*>(&h1);
    reinterpret_cast<uint2*>(g_Hh)[t] = u;
}

// acc (8 floats) += 8 halves packed in uint4
__device__ __forceinline__ void acc8h(float4& a, float4& b, uint4 u) {
    float2 f0 = __half22float2(*reinterpret_cast<__half2*>(&u.x));
    float2 f1 = __half22float2(*reinterpret_cast<__half2*>(&u.y));
    float2 f2 = __half22float2(*reinterpret_cast<__half2*>(&u.z));
    float2 f3 = __half22float2(*reinterpret_cast<__half2*>(&u.w));
    a.x += f0.x; a.y += f0.y; a.z += f1.x; a.w += f1.y;
    b.x += f2.x; b.y += f2.y; b.z += f3.x; b.w += f3.y;
}
// pairwise fp16 add of two uint4s (4x HADD2)
__device__ __forceinline__ uint4 hadd2x4(uint4 a, uint4 b) {
    uint4 r;
    *reinterpret_cast<__half2*>(&r.x) = __hadd2(*reinterpret_cast<__half2*>(&a.x),
                                                *reinterpret_cast<__half2*>(&b.x));
    *reinterpret_cast<__half2*>(&r.y) = __hadd2(*reinterpret_cast<__half2*>(&a.y),
                                                *reinterpret_cast<__half2*>(&b.y));
    *reinterpret_cast<__half2*>(&r.z) = __hadd2(*reinterpret_cast<__half2*>(&a.z),
                                                *reinterpret_cast<__half2*>(&b.z));
    *reinterpret_cast<__half2*>(&r.w) = __hadd2(*reinterpret_cast<__half2*>(&a.w),
                                                *reinterpret_cast<__half2*>(&b.w));
    return r;
}

// Gather: AGGh[n] = half( (sum_{s in adj[n]} H[s]) * nin[n] )
// NN*8 threads: thread j of node n owns uint4 chunk j (8 halves, 16B).
// Depth-2 fp16 tree (groups of 4 summed in fp16) then fp32 accumulate.
template <int LAYER>
__global__ void __launch_bounds__(256) k_agg(const int* __restrict__ src,
                                             const int* __restrict__ dst) {
    int t = blockIdx.x * blockDim.x + threadIdx.x;
    if (t >= NN * 8) return;
    int n = t >> 3, j = t & 7;
    const uint4* Hv = reinterpret_cast<const uint4*>(LAYER == 1 ? g_Hh : g_H2h);
    int cnt = g_cnt[n];
    int lim = cnt < ADJ_STRIDE ? cnt : ADJ_STRIDE;
    const int* lst = &g_adj[n * ADJ_STRIDE];
    float4 accA = make_float4(0.f, 0.f, 0.f, 0.f);
    float4 accB = make_float4(0.f, 0.f, 0.f, 0.f);
    int k = 0;
    for (; k + 4 <= lim; k += 4) {
        int4 s4 = *reinterpret_cast<const int4*>(&lst[k]);
        uint4 u0 = Hv[s4.x * 8 + j];
        uint4 u1 = Hv[s4.y * 8 + j];
        uint4 u2 = Hv[s4.z * 8 + j];
        uint4 u3 = Hv[s4.w * 8 + j];
        acc8h(accA, accB, hadd2x4(hadd2x4(u0, u1), hadd2x4(u2, u3)));
    }
    for (; k + 2 <= lim; k += 2) {
        uint4 u0 = Hv[__ldg(&lst[k]) * 8 + j];
        uint4 u1 = Hv[__ldg(&lst[k + 1]) * 8 + j];
        acc8h(accA, accB, hadd2x4(u0, u1));
    }
    if (k < lim) acc8h(accA, accB, Hv[__ldg(&lst[k]) * 8 + j]);
    if (cnt > ADJ_STRIDE) {                 // overflow (expected none)
        int oc = g_ovf_cnt; if (oc > OVF_CAP) oc = OVF_CAP;
        for (int i = 0; i < oc; i++) {
            int e = g_ovf[i];
            if (dst[e] == n) acc8h(accA, accB, Hv[src[e] * 8 + j]);
        }
    }
    float s = g_nin[n];
    __half2 h0 = __floats2half2_rn(accA.x * s, accA.y * s);
    __half2 h1 = __floats2half2_rn(accA.z * s, accA.w * s);
    __half2 h2 = __floats2half2_rn(accB.x * s, accB.y * s);
    __half2 h3 = __floats2half2_rn(accB.z * s, accB.w * s);
    uint4 u;
    u.x = *reinterpret_cast<unsigned*>(&h0);
    u.y = *reinterpret_cast<unsigned*>(&h1);
    u.z = *reinterpret_cast<unsigned*>(&h2);
    u.w = *reinterpret_cast<unsigned*>(&h3);
    reinterpret_cast<uint4*>(g_AGGh)[t] = u;
}

// ---------------------------------------------------------------------------
// Warp-MMA GEMM (HMMA): D(128x64) = A(128x64) @ W(64x64)
__device__ __forceinline__ unsigned smem_u32(const void* p) {
    unsigned a;
    asm("{ .reg .u64 t; cvta.to.shared.u64 t, %1; cvt.u32.u64 %0, t; }" : "=r"(a) : "l"(p));
    return a;
}
__device__ __forceinline__ void ldmx4(unsigned& r0, unsigned& r1, unsigned& r2,
                                      unsigned& r3, unsigned addr) {
    asm volatile("ldmatrix.sync.aligned.m8n8.x4.shared.b16 {%0,%1,%2,%3}, [%4];"
                 : "=r"(r0), "=r"(r1), "=r"(r2), "=r"(r3) : "r"(addr));
}
__device__ __forceinline__ void mma16816(float* d, unsigned a0, unsigned a1,
                                         unsigned a2, unsigned a3,
                                         unsigned b0, unsigned b1) {
    asm volatile(
        "mma.sync.aligned.m16n8k16.row.col.f32.f16.f16.f32 "
        "{%0,%1,%2,%3}, {%4,%5,%6,%7}, {%8,%9}, {%0,%1,%2,%3};"
        : "+f"(d[0]), "+f"(d[1]), "+f"(d[2]), "+f"(d[3])
        : "r"(a0), "r"(a1), "r"(a2), "r"(a3), "r"(b0), "r"(b1));
}

template <int LAYER>
__global__ void __launch_bounds__(128)
k_gemm_mma(const float* __restrict__ bias, float* __restrict__ out_param) {
    __shared__ __align__(16) __half sA[128 * 64];
    __shared__ __align__(16) __half sB[64 * 64];
    __shared__ float bs[64];

    const int t = threadIdx.x;
    const int wid = t >> 5, lane = t & 31;

    // B: pre-transposed fp16 weights -> vectorized swizzled copy (4x16B/thread)
    {
        const uint4* wt4 = reinterpret_cast<const uint4*>(g_Wt[LAYER - 1]);
        #pragma unroll
        for (int q = 0; q < 4; q++) {
            int idx = q * 128 + t;
            uint4 v = wt4[idx];
            *reinterpret_cast<uint4*>(
                reinterpret_cast<char*>(sB) + SW128(idx * 16)) = v;
        }
    }
    if (t < 64) bs[t] = bias[t];

    int gr = blockIdx.x * 128 + t;
    {
        const uint4* a4 = reinterpret_cast<const uint4*>(g_AGGh);
        #pragma unroll
        for (int ch = 0; ch < 8; ch++) {
            uint4 v = make_uint4(0u, 0u, 0u, 0u);
            if (gr < NN) v = a4[gr * 8 + ch];
            *reinterpret_cast<uint4*>(
                reinterpret_cast<char*>(sA) + SW128(t * 128 + ch * 16)) = v;
        }
    }
    __syncthreads();

    const unsigned baseA = smem_u32(sA);
    const unsigned baseB = smem_u32(sB);
    const int lrow = lane & 15;
    const int lcol = (lane >> 4) * 16;

    float d[2][8][4];
    #pragma unroll
    for (int i = 0; i < 2; i++)
        #pragma unroll
        for (int j = 0; j < 8; j++)
            #pragma unroll
            for (int q = 0; q < 4; q++) d[i][j][q] = 0.f;

    #pragma unroll
    for (int kk = 0; kk < 4; kk++) {
        unsigned a[2][4];
        #pragma unroll
        for (int i = 0; i < 2; i++) {
            int row = wid * 32 + i * 16 + lrow;
            unsigned addr = baseA + SW128(row * 128 + kk * 32 + lcol);
            ldmx4(a[i][0], a[i][1], a[i][2], a[i][3], addr);
        }
        #pragma unroll
        for (int p = 0; p < 4; p++) {
            unsigned r0, r1, r2, r3;
            int nrow = p * 16 + lrow;
            unsigned addr = baseB + SW128(nrow * 128 + kk * 32 + lcol);
            ldmx4(r0, r1, r2, r3, addr);
            #pragma unroll
            for (int i = 0; i < 2; i++) {
                mma16816(d[i][p * 2 + 0], a[i][0], a[i][1], a[i][2], a[i][3], r0, r2);
                mma16816(d[i][p * 2 + 1], a[i][0], a[i][1], a[i][2], a[i][3], r1, r3);
            }
        }
    }

    const int g   = lane >> 2;
    const int tid = lane & 3;
    #pragma unroll
    for (int i = 0; i < 2; i++) {
        #pragma unroll
        for (int half = 0; half < 2; half++) {
            int row = blockIdx.x * 128 + wid * 32 + i * 16 + g + half * 8;
            if (row >= NN) continue;
            float no = (LAYER == 1) ? g_nout[row] : 0.f;
            #pragma unroll
            for (int j = 0; j < 8; j++) {
                int c = j * 8 + tid * 2;
                float v0 = d[i][j][half * 2 + 0] + bs[c];
                float v1 = d[i][j][half * 2 + 1] + bs[c + 1];
                if (LAYER == 1) {
                    v0 = fmaxf(v0, 0.f) * no;
                    v1 = fmaxf(v1, 0.f) * no;
                    __half2 h = __floats2half2_rn(v0, v1);
                    *reinterpret_cast<__half2*>(&g_H2h[row * DD + c]) = h;
                } else {
                    *reinterpret_cast<float2*>(&out_param[row * DD + c]) =
                        make_float2(v0, v1);
                }
            }
        }
    }
}

// ---------------------------------------------------------------------------
extern "C" void kernel_launch(void* const* d_in, const int* in_sizes, int n_in,
                              void* d_out, int out_size) {
    const float* feats = 0;
    const int *edgeA = 0, *edgeB = 0;
    const float* Wv[2] = {0, 0};
    const float* bv[2] = {0, 0};
    int wi = 0, bi = 0;
    for (int i = 0; i < n_in; i++) {
        int sz = in_sizes[i];
        if (sz == NN * DD)      feats = (const float*)d_in[i];
        else if (sz == NE)      { if (!edgeA) edgeA = (const int*)d_in[i]; else edgeB = (const int*)d_in[i]; }
        else if (sz == DD * DD) { if (wi < 2) Wv[wi++] = (const float*)d_in[i]; }
        else if (sz == DD)      { if (bi < 2) bv[bi++] = (const float*)d_in[i]; }
    }
    const int* src = edgeA;   // insertion order: src precedes dst (verified R4)
    const int* dst = edgeB;
    float* out = (float*)d_out;

    const int T = 256;
    const int g_nodes  = (NN + T - 1) / T;
    const int g_edges4 = (NE / 4 + T - 1) / T;
    const int g_vec    = (NN * 16 + T - 1) / T;   // k_scale
    const int g_agg    = (NN * 8 + T - 1) / T;    // k_agg (uint4 lanes)

    k_zero <<<g_nodes,  T>>>(Wv[0], Wv[1]);       // counters + W transpose
    k_build<<<g_edges4, T>>>((const int4*)src, (const int4*)dst);
    k_norm <<<g_nodes,  T>>>();
    k_scale<<<g_vec,    T>>>((const float4*)feats);

    k_agg<1>     <<<g_agg, T>>>(src, dst);
    k_gemm_mma<1><<<NTM, 128>>>(bv[0], 0);

    k_agg<2>     <<<g_agg, T>>>(src, dst);
    k_gemm_mma<2><<<NTM, 128>>>(bv[1], out);
}

// round 13
// speedup vs baseline: 1.2662x; 1.0766x over previous
#include <cuda_runtime.h>
#include <cuda_fp16.h>

#define NN 100000
#define NE 1200000
#define DD 64
#define ADJ_STRIDE 32
#define OVF_CAP 8192
#define NTF 3125                // 100000/32 fused tiles (exact)
#define SW128(o) ((o) ^ ((((o) >> 3)) & 0x70))

typedef unsigned long long u64;

// Scratch (device globals — no allocation allowed)
__device__ __half g_Hh  [NN * DD];        // layer-1 gather source (feats*nout)
__device__ __half g_H2h [NN * DD];        // layer-2 gather source
__device__ __half g_Wt[2][DD * DD];       // pre-transposed fp16 weights [c*64+k]
__device__ int   g_degout[NN];
__device__ int   g_cnt[NN];
__device__ float g_nout[NN];
__device__ float g_nin[NN];
__device__ int   g_adj[NN * ADJ_STRIDE];
__device__ int   g_ovf[OVF_CAP];
__device__ int   g_ovf_cnt;

// ---------------------------------------------------------------------------
// zero counters + pre-transpose weights (merged: saves a launch)
__global__ void k_zero(const float* __restrict__ W1, const float* __restrict__ W2) {
    int i = blockIdx.x * blockDim.x + threadIdx.x;
    if (i < NN) { g_degout[i] = 0; g_cnt[i] = 0; }
    if (i == 0) g_ovf_cnt = 0;
    if (i < 2 * DD * DD) {
        int l = i >> 12;
        int r = i & 4095;
        int c = r >> 6, k = r & 63;
        const float* W = l ? W2 : W1;
        g_Wt[l][c * 64 + k] = __float2half_rn(W[k * 64 + c]);
    }
}

// 4 edges per thread (int4 loads) for atomic-latency MLP.
__global__ void k_build(const int4* __restrict__ src4, const int4* __restrict__ dst4) {
    int e4 = blockIdx.x * blockDim.x + threadIdx.x;
    if (e4 >= NE / 4) return;
    int4 s = src4[e4];
    int4 d = dst4[e4];
    atomicAdd(&g_degout[s.x], 1);
    atomicAdd(&g_degout[s.y], 1);
    atomicAdd(&g_degout[s.z], 1);
    atomicAdd(&g_degout[s.w], 1);
    int c0 = atomicAdd(&g_cnt[d.x], 1);
    int c1 = atomicAdd(&g_cnt[d.y], 1);
    int c2 = atomicAdd(&g_cnt[d.z], 1);
    int c3 = atomicAdd(&g_cnt[d.w], 1);
    int base = e4 * 4;
    if (c0 < ADJ_STRIDE) g_adj[d.x * ADJ_STRIDE + c0] = s.x;
    else { int o = atomicAdd(&g_ovf_cnt, 1); if (o < OVF_CAP) g_ovf[o] = base; }
    if (c1 < ADJ_STRIDE) g_adj[d.y * ADJ_STRIDE + c1] = s.y;
    else { int o = atomicAdd(&g_ovf_cnt, 1); if (o < OVF_CAP) g_ovf[o] = base + 1; }
    if (c2 < ADJ_STRIDE) g_adj[d.z * ADJ_STRIDE + c2] = s.z;
    else { int o = atomicAdd(&g_ovf_cnt, 1); if (o < OVF_CAP) g_ovf[o] = base + 2; }
    if (c3 < ADJ_STRIDE) g_adj[d.w * ADJ_STRIDE + c3] = s.w;
    else { int o = atomicAdd(&g_ovf_cnt, 1); if (o < OVF_CAP) g_ovf[o] = base + 3; }
}

// norms from final counts (tiny)
__global__ void k_norm() {
    int i = blockIdx.x * blockDim.x + threadIdx.x;
    if (i < NN) {
        g_nout[i] = rsqrtf(fmaxf((float)g_degout[i], 1.0f));
        g_nin[i]  = rsqrtf(fmaxf((float)g_cnt[i],  1.0f));
    }
}

// Pure stream: Hh = half(feats * nout[row]); 2 independent float4 chains.
__global__ void k_scale(const float4* __restrict__ feats) {
    int t0 = (blockIdx.x * blockDim.x + threadIdx.x) * 2;
    if (t0 >= NN * 16) return;
    float4 v0 = feats[t0];
    float4 v1 = feats[t0 + 1];
    float s0 = g_nout[t0 >> 4];
    float s1 = g_nout[(t0 + 1) >> 4];
    __half2 a0 = __floats2half2_rn(v0.x * s0, v0.y * s0);
    __half2 a1 = __floats2half2_rn(v0.z * s0, v0.w * s0);
    __half2 b0 = __floats2half2_rn(v1.x * s1, v1.y * s1);
    __half2 b1 = __floats2half2_rn(v1.z * s1, v1.w * s1);
    uint4 u;
    u.x = *reinterpret_cast<unsigned*>(&a0);
    u.y = *reinterpret_cast<unsigned*>(&a1);
    u.z = *reinterpret_cast<unsigned*>(&b0);
    u.w = *reinterpret_cast<unsigned*>(&b1);
    reinterpret_cast<uint4*>(g_Hh)[t0 >> 1] = u;
}

// acc (8 floats) += 8 halves packed in uint4
__device__ __forceinline__ void acc8h(float4& a, float4& b, uint4 u) {
    float2 f0 = __half22float2(*reinterpret_cast<__half2*>(&u.x));
    float2 f1 = __half22float2(*reinterpret_cast<__half2*>(&u.y));
    float2 f2 = __half22float2(*reinterpret_cast<__half2*>(&u.z));
    float2 f3 = __half22float2(*reinterpret_cast<__half2*>(&u.w));
    a.x += f0.x; a.y += f0.y; a.z += f1.x; a.w += f1.y;
    b.x += f2.x; b.y += f2.y; b.z += f3.x; b.w += f3.y;
}
// pairwise fp16 add of two uint4s (4x HADD2)
__device__ __forceinline__ uint4 hadd2x4(uint4 a, uint4 b) {
    uint4 r;
    *reinterpret_cast<__half2*>(&r.x) = __hadd2(*reinterpret_cast<__half2*>(&a.x),
                                                *reinterpret_cast<__half2*>(&b.x));
    *reinterpret_cast<__half2*>(&r.y) = __hadd2(*reinterpret_cast<__half2*>(&a.y),
                                                *reinterpret_cast<__half2*>(&b.y));
    *reinterpret_cast<__half2*>(&r.z) = __hadd2(*reinterpret_cast<__half2*>(&a.z),
                                                *reinterpret_cast<__half2*>(&b.z));
    *reinterpret_cast<__half2*>(&r.w) = __hadd2(*reinterpret_cast<__half2*>(&a.w),
                                                *reinterpret_cast<__half2*>(&b.w));
    return r;
}

__device__ __forceinline__ unsigned smem_u32(const void* p) {
    unsigned a;
    asm("{ .reg .u64 t; cvta.to.shared.u64 t, %1; cvt.u32.u64 %0, t; }" : "=r"(a) : "l"(p));
    return a;
}
__device__ __forceinline__ void ldmx4(unsigned& r0, unsigned& r1, unsigned& r2,
                                      unsigned& r3, unsigned addr) {
    asm volatile("ldmatrix.sync.aligned.m8n8.x4.shared.b16 {%0,%1,%2,%3}, [%4];"
                 : "=r"(r0), "=r"(r1), "=r"(r2), "=r"(r3) : "r"(addr));
}
__device__ __forceinline__ void mma16816(float* d, unsigned a0, unsigned a1,
                                         unsigned a2, unsigned a3,
                                         unsigned b0, unsigned b1) {
    asm volatile(
        "mma.sync.aligned.m16n8k16.row.col.f32.f16.f16.f32 "
        "{%0,%1,%2,%3}, {%4,%5,%6,%7}, {%8,%9}, {%0,%1,%2,%3};"
        : "+f"(d[0]), "+f"(d[1]), "+f"(d[2]), "+f"(d[3])
        : "r"(a0), "r"(a1), "r"(a2), "r"(a3), "r"(b0), "r"(b1));
}

// ---------------------------------------------------------------------------
// Fused layer: gather 32 nodes -> smem (scaled by nin), HMMA 32x64 @ 64x64,
// fused epilogue. 256 threads = 8 warps; warp owns 16x16 output quadrant.
//   LAYER==1: out = g_H2h (fp16), epi = relu(.)*nout
//   LAYER==2: out = out_param (fp32 d_out), epi = identity
template <int LAYER>
__global__ void __launch_bounds__(256)
k_fused(const int* __restrict__ src, const int* __restrict__ dst,
        const float* __restrict__ bias, float* __restrict__ out_param) {
    __shared__ __align__(16) __half sA[32 * 64];    // 4KB swizzled
    __shared__ __align__(16) __half sB[64 * 64];    // 8KB swizzled
    __shared__ float bs[64];

    const int t = threadIdx.x;
    const int wid = t >> 5, lane = t & 31;
    const uint4* Hv = reinterpret_cast<const uint4*>(LAYER == 1 ? g_Hh : g_H2h);

    // B: pre-transposed fp16 weights -> swizzled smem (2x16B per thread)
    {
        const uint4* wt4 = reinterpret_cast<const uint4*>(g_Wt[LAYER - 1]);
        #pragma unroll
        for (int q = 0; q < 2; q++) {
            int idx = q * 256 + t;
            uint4 v = wt4[idx];
            *reinterpret_cast<uint4*>(
                reinterpret_cast<char*>(sB) + SW128(idx * 16)) = v;
        }
    }
    if (t < 64) bs[t] = bias[t];

    // ---- gather phase: 8 threads per node, thread j owns 16B chunk j ----
    {
        int n = blockIdx.x * 32 + (t >> 3);     // NTF*32 == NN exactly
        int j = t & 7;
        int cnt = g_cnt[n];
        int lim = cnt < ADJ_STRIDE ? cnt : ADJ_STRIDE;
        const int* lst = &g_adj[n * ADJ_STRIDE];
        float4 accA = make_float4(0.f, 0.f, 0.f, 0.f);
        float4 accB = make_float4(0.f, 0.f, 0.f, 0.f);
        int k = 0;
        for (; k + 4 <= lim; k += 4) {
            int4 s4 = *reinterpret_cast<const int4*>(&lst[k]);
            uint4 u0 = Hv[s4.x * 8 + j];
            uint4 u1 = Hv[s4.y * 8 + j];
            uint4 u2 = Hv[s4.z * 8 + j];
            uint4 u3 = Hv[s4.w * 8 + j];
            acc8h(accA, accB, hadd2x4(hadd2x4(u0, u1), hadd2x4(u2, u3)));
        }
        for (; k + 2 <= lim; k += 2) {
            uint4 u0 = Hv[__ldg(&lst[k]) * 8 + j];
            uint4 u1 = Hv[__ldg(&lst[k + 1]) * 8 + j];
            acc8h(accA, accB, hadd2x4(u0, u1));
        }
        if (k < lim) acc8h(accA, accB, Hv[__ldg(&lst[k]) * 8 + j]);
        if (cnt > ADJ_STRIDE) {                 // overflow (expected none)
            int oc = g_ovf_cnt; if (oc > OVF_CAP) oc = OVF_CAP;
            for (int i = 0; i < oc; i++) {
                int e = g_ovf[i];
                if (dst[e] == n) acc8h(accA, accB, Hv[src[e] * 8 + j]);
            }
        }
        float s = g_nin[n];
        __half2 h0 = __floats2half2_rn(accA.x * s, accA.y * s);
        __half2 h1 = __floats2half2_rn(accA.z * s, accA.w * s);
        __half2 h2 = __floats2half2_rn(accB.x * s, accB.y * s);
        __half2 h3 = __floats2half2_rn(accB.z * s, accB.w * s);
        uint4 u;
        u.x = *reinterpret_cast<unsigned*>(&h0);
        u.y = *reinterpret_cast<unsigned*>(&h1);
        u.z = *reinterpret_cast<unsigned*>(&h2);
        u.w = *reinterpret_cast<unsigned*>(&h3);
        *reinterpret_cast<uint4*>(
            reinterpret_cast<char*>(sA) + SW128((t >> 3) * 128 + j * 16)) = u;
    }
    __syncthreads();

    // ---- MMA phase: warp = (row-half i, col-group p) of 32x64 output ----
    const unsigned baseA = smem_u32(sA);
    const unsigned baseB = smem_u32(sB);
    const int i = wid >> 2;                 // 0..1 (16-row half)
    const int p = wid & 3;                  // 0..3 (16-col group)
    const int lrow = lane & 15;
    const int lcol = (lane >> 4) * 16;

    float d[2][4];
    #pragma unroll
    for (int jj = 0; jj < 2; jj++)
        #pragma unroll
        for (int q = 0; q < 4; q++) d[jj][q] = 0.f;

    #pragma unroll
    for (int kk = 0; kk < 4; kk++) {
        unsigned a0, a1, a2, a3;
        ldmx4(a0, a1, a2, a3,
              baseA + SW128((i * 16 + lrow) * 128 + kk * 32 + lcol));
        unsigned r0, r1, r2, r3;
        ldmx4(r0, r1, r2, r3,
              baseB + SW128((p * 16 + lrow) * 128 + kk * 32 + lcol));
        mma16816(d[0], a0, a1, a2, a3, r0, r2);
        mma16816(d[1], a0, a1, a2, a3, r1, r3);
    }

    // ---- epilogue: warp's 16x16 quadrant ----
    const int g   = lane >> 2;
    const int tid = lane & 3;
    #pragma unroll
    for (int jj = 0; jj < 2; jj++) {
        #pragma unroll
        for (int half = 0; half < 2; half++) {
            int row = blockIdx.x * 32 + i * 16 + g + half * 8;
            int c = p * 16 + jj * 8 + tid * 2;
            float v0 = d[jj][half * 2 + 0] + bs[c];
            float v1 = d[jj][half * 2 + 1] + bs[c + 1];
            if (LAYER == 1) {
                float no = g_nout[row];
                v0 = fmaxf(v0, 0.f) * no;
                v1 = fmaxf(v1, 0.f) * no;
                __half2 h = __floats2half2_rn(v0, v1);
                *reinterpret_cast<__half2*>(&g_H2h[row * DD + c]) = h;
            } else {
                *reinterpret_cast<float2*>(&out_param[row * DD + c]) =
                    make_float2(v0, v1);
            }
        }
    }
}

// ---------------------------------------------------------------------------
extern "C" void kernel_launch(void* const* d_in, const int* in_sizes, int n_in,
                              void* d_out, int out_size) {
    const float* feats = 0;
    const int *edgeA = 0, *edgeB = 0;
    const float* Wv[2] = {0, 0};
    const float* bv[2] = {0, 0};
    int wi = 0, bi = 0;
    for (int i = 0; i < n_in; i++) {
        int sz = in_sizes[i];
        if (sz == NN * DD)      feats = (const float*)d_in[i];
        else if (sz == NE)      { if (!edgeA) edgeA = (const int*)d_in[i]; else edgeB = (const int*)d_in[i]; }
        else if (sz == DD * DD) { if (wi < 2) Wv[wi++] = (const float*)d_in[i]; }
        else if (sz == DD)      { if (bi < 2) bv[bi++] = (const float*)d_in[i]; }
    }
    const int* src = edgeA;   // insertion order: src precedes dst (verified R4)
    const int* dst = edgeB;
    float* out = (float*)d_out;

    const int T = 256;
    const int g_nodes  = (NN + T - 1) / T;
    const int g_edges4 = (NE / 4 + T - 1) / T;
    const int g_scale  = (NN * 8 + T - 1) / T;    // 2 float4 per thread

    k_zero <<<g_nodes,  T>>>(Wv[0], Wv[1]);       // counters + W transpose
    k_build<<<g_edges4, T>>>((const int4*)src, (const int4*)dst);
    k_norm <<<g_nodes,  T>>>();
    k_scale<<<g_scale,  T>>>((const float4*)feats);

    k_fused<1><<<NTF, T>>>(src, dst, bv[0], 0);
    k_fused<2><<<NTF, T>>>(src, dst, bv[1], out);
}